// round 3
// baseline (speedup 1.0000x reference)
#include <cuda_runtime.h>
#include <cuda_bf16.h>
#include <stdint.h>

// ---------------- problem constants ----------------
#define BATCH   64
#define HDIM    512
#define WDIM    512
#define NPIX    (HDIM*WDIM)          // 262144
#define NIMG    (2*BATCH)            // 128 (pred images then target images)
#define NPTS    1000                 // SAMPLE_POINTS
#define NBINS   6144
#define CANDCAP 4096

// ---------------- device scratch (static, allowed) ----------------
__device__ uint32_t g_keys[256];                       // split keys (pairs)
__device__ float    g_prob[(size_t)BATCH*NPIX];        // sigmoid(pred)
__device__ uint32_t g_validbits[NIMG*(NPIX/32)];       // bit-packed valid mask
__device__ uint32_t g_scores[(size_t)NIMG*NPIX];       // float bits of score
__device__ uint32_t g_hist[NIMG*NBINS];
struct CutInfo { uint32_t bin, G, need, nvalid; };
__device__ CutInfo  g_cut[NIMG];
__device__ uint32_t g_selcnt[NIMG];
__device__ uint32_t g_candcnt[NIMG];
__device__ unsigned long long g_cand[(size_t)NIMG*CANDCAP];
__device__ float2   g_pts[NIMG*NPTS];
__device__ unsigned char g_pv[NIMG*NPTS];
__device__ float    g_hd[BATCH];

// ---------------- threefry2x32 (exact JAX semantics) ----------------
__device__ __forceinline__ uint32_t rotl32(uint32_t x, int r) {
    return __funnelshift_l(x, x, r);   // single SHF
}
__device__ __forceinline__ void threefry2x32(uint32_t k0, uint32_t k1,
                                             uint32_t x0, uint32_t x1,
                                             uint32_t& o0, uint32_t& o1) {
    uint32_t ks2 = k0 ^ k1 ^ 0x1BD11BDAu;
    x0 += k0; x1 += k1;
#define TF_RND(r) { x0 += x1; x1 = rotl32(x1, r); x1 ^= x0; }
    TF_RND(13) TF_RND(15) TF_RND(26) TF_RND(6)   x0 += k1;  x1 += ks2 + 1u;
    TF_RND(17) TF_RND(29) TF_RND(16) TF_RND(24)  x0 += ks2; x1 += k0  + 2u;
    TF_RND(13) TF_RND(15) TF_RND(26) TF_RND(6)   x0 += k0;  x1 += k1  + 3u;
    TF_RND(17) TF_RND(29) TF_RND(16) TF_RND(24)  x0 += k1;  x1 += ks2 + 4u;
    TF_RND(13) TF_RND(15) TF_RND(26) TF_RND(6)   x0 += ks2; x1 += k0  + 5u;
#undef TF_RND
    o0 = x0; o1 = x1;
}
__device__ __forceinline__ float bits_to_uniform(uint32_t bits) {
    // jax.random.uniform float32: ((bits>>9) | 0x3F800000) bitcast - 1.0f
    return __uint_as_float((bits >> 9) | 0x3F800000u) - 1.0f;
}

// monotone bin transform of positive-float score bits
__device__ __forceinline__ int bin_of(uint32_t bits) {
    if (bits >= 0x40000000u) {               // valid scores: [2, 3)
        int v = 2048 + (int)((bits - 0x40000000u) >> 10);
        return v > (NBINS - 1) ? (NBINS - 1) : v;
    }
    return (int)(bits >> 19);                // invalid: [0,1) -> bins < 2048
}

// ---------------- kernels ----------------
__global__ void k_zero() {
    int i = blockIdx.x * blockDim.x + threadIdx.x;
    if (i < NIMG * NBINS) g_hist[i] = 0;
    if (i < NIMG) { g_selcnt[i] = 0; g_candcnt[i] = 0; }
}

// PARTITIONABLE split(key(1), 128) ("fold-like"):
//   key_i = threefry2x32(k0=0, k1=1, hi=0, lo=i); full 2x32 output is the new key.
__global__ void k_keys() {
    int i = threadIdx.x;
    if (i < 128) {
        uint32_t o0, o1;
        threefry2x32(0u, 1u, 0u, (uint32_t)i, o0, o1);
        g_keys[2*i]     = o0;
        g_keys[2*i + 1] = o1;
    }
}

__global__ void k_sigmoid(const float* __restrict__ logits) {
    int i = blockIdx.x * blockDim.x + threadIdx.x;
    if (i < BATCH * NPIX) {
        float x = logits[i];
        g_prob[i] = 1.0f / (1.0f + expf(-x));
    }
}

// Sobel boundary -> valid bits (32 pixels per thread, sliding window)
__global__ void k_valid(const float* __restrict__ target) {
    int w = blockIdx.x * blockDim.x + threadIdx.x;
    if (w >= NIMG * (NPIX / 32)) return;
    int b    = w >> 13;          // / 8192
    int widx = w & 8191;
    int p0 = widx << 5;
    int r  = p0 >> 9;
    int c0 = p0 & 511;
    const float* src = (b < BATCH) ? (g_prob + (size_t)b * NPIX)
                                   : (target + (size_t)(b - BATCH) * NPIX);
    auto ld = [&](int rr, int cc) -> float {
        if (rr < 0 || rr >= HDIM || cc < 0 || cc >= WDIM) return 0.0f;
        return __ldg(&src[(rr << 9) + cc]);
    };
    float L0 = ld(r-1, c0-1), L1 = ld(r, c0-1), L2 = ld(r+1, c0-1);
    float M0 = ld(r-1, c0  ), M1 = ld(r, c0  ), M2 = ld(r+1, c0  );
    uint32_t out = 0;
#pragma unroll 4
    for (int j = 0; j < 32; j++) {
        int c = c0 + j;
        float R0 = ld(r-1, c+1), R1 = ld(r, c+1), R2 = ld(r+1, c+1);
        float gx = (R0 - L0) + 2.0f * (R1 - L1) + (R2 - L2);
        float gy = (L2 + 2.0f * M2 + R2) - (L0 + 2.0f * M0 + R0);
        float bm = sqrtf(gx * gx + gy * gy + 1e-8f);
        if (bm > 0.1f) out |= (1u << j);
        L0 = M0; L1 = M1; L2 = M2;
        M0 = R0; M1 = R1; M2 = R2;
    }
    g_validbits[w] = out;
}

// PARTITIONABLE uniform bits: per-pixel 64-bit counter (hi=0, lo=i),
// bits = o0 ^ o1. One thread per pixel. Also builds per-image histogram.
__global__ void k_score() {
    __shared__ uint32_t sh[NBINS];
    int tid = threadIdx.x;
    for (int q = tid; q < NBINS; q += blockDim.x) sh[q] = 0;
    __syncthreads();
    int b = blockIdx.y;
    int i = blockIdx.x * blockDim.x + tid;         // 0..NPIX-1
    uint32_t k0 = g_keys[2*b], k1 = g_keys[2*b + 1];
    uint32_t o0, o1;
    threefry2x32(k0, k1, 0u, (uint32_t)i, o0, o1);
    uint32_t rb = o0 ^ o1;
    float u = bits_to_uniform(rb);
    uint32_t vw = g_validbits[b * (NPIX/32) + (i >> 5)];
    bool v = (vw >> (i & 31)) & 1u;
    float s = (v ? 2.0f : 0.0f) + u;
    uint32_t sb = __float_as_uint(s);
    g_scores[(size_t)b * NPIX + i] = sb;
    atomicAdd(&sh[bin_of(sb)], 1u);
    __syncthreads();
    for (int q = tid; q < NBINS; q += blockDim.x) {
        uint32_t cv = sh[q];
        if (cv) atomicAdd(&g_hist[b * NBINS + q], cv);
    }
}

__global__ void k_cutoff() {
    int b = threadIdx.x;
    if (b >= NIMG) return;
    const uint32_t* h = &g_hist[b * NBINS];
    uint32_t nvalid = 0;
    for (int q = 2048; q < NBINS; q++) nvalid += h[q];
    uint32_t cum = 0, G = 0; int bin = 0;
    for (int q = NBINS - 1; q >= 0; q--) {
        uint32_t c = h[q];
        if (cum + c >= (uint32_t)NPTS) { bin = q; G = cum; break; }
        cum += c;
    }
    CutInfo ci; ci.bin = (uint32_t)bin; ci.G = G; ci.need = NPTS - G; ci.nvalid = nvalid;
    g_cut[b] = ci;
}

__global__ void k_compact() {
    int b   = blockIdx.y;
    int idx = blockIdx.x * blockDim.x + threadIdx.x;   // 0..NPIX-1
    uint32_t bits = g_scores[(size_t)b * NPIX + idx];
    int bin = bin_of(bits);
    CutInfo c = g_cut[b];
    if (bin > (int)c.bin) {
        uint32_t pos = atomicAdd(&g_selcnt[b], 1u);
        g_pts[b * NPTS + pos] = make_float2((float)(idx >> 9), (float)(idx & 511));
        g_pv[b * NPTS + pos]  = (bits >= 0x40000000u);
    } else if (bin == (int)c.bin) {
        uint32_t q = atomicAdd(&g_candcnt[b], 1u);
        if (q < CANDCAP)
            g_cand[(size_t)b * CANDCAP + q] =
                (((unsigned long long)bits) << 32) | (unsigned long long)(~(uint32_t)idx);
    }
}

// per image: sort cutoff-bin candidates (score desc, index asc), emit remainder
__global__ void k_sort_emit() {
    __shared__ unsigned long long s[CANDCAP];
    int b = blockIdx.x, tid = threadIdx.x, nt = blockDim.x;
    CutInfo c = g_cut[b];
    uint32_t cnt  = g_candcnt[b]; if (cnt > CANDCAP) cnt = CANDCAP;
    uint32_t need = c.need;       if (need > cnt)    need = cnt;
    int n = 2; while (n < (int)cnt) n <<= 1;
    for (int i = tid; i < n; i += nt)
        s[i] = (i < (int)cnt) ? g_cand[(size_t)b * CANDCAP + i] : 0ull;
    __syncthreads();
    for (int k = 2; k <= n; k <<= 1) {
        for (int j = k >> 1; j > 0; j >>= 1) {
            for (int i = tid; i < n; i += nt) {
                int ixj = i ^ j;
                if (ixj > i) {
                    unsigned long long a = s[i], bb = s[ixj];
                    bool up = ((i & k) == 0);
                    if ((a > bb) == up) { s[i] = bb; s[ixj] = a; }
                }
            }
            __syncthreads();
        }
    }
    // ascending sort -> top `need` at the tail (ties resolved to smaller idx first)
    for (uint32_t j = tid; j < need; j += nt) {
        unsigned long long key = s[n - 1 - j];
        uint32_t bits = (uint32_t)(key >> 32);
        uint32_t idx  = ~(uint32_t)key;
        uint32_t pos  = c.G + j;
        g_pts[b * NPTS + pos] = make_float2((float)(idx >> 9), (float)(idx & 511));
        g_pv[b * NPTS + pos]  = (bits >= 0x40000000u);
    }
    if (c.nvalid == 0) {   // has_any == False path
        __syncthreads();
        for (int j = tid; j < NPTS; j += nt) {
            g_pts[b * NPTS + j] = make_float2(256.0f, 256.0f);
            g_pv[b * NPTS + j]  = (j == 0);
        }
    }
}

__global__ void __launch_bounds__(1024) k_hausdorff() {
    int b = blockIdx.x;                 // 0..63
    __shared__ float px[NPTS], py[NPTS], tx[NPTS], ty[NPTS];
    __shared__ unsigned char pvv[NPTS], tvv[NPTS];
    __shared__ float cvx[NPTS], cvy[NPTS], cpx[NPTS], cpy[NPTS];
    __shared__ int sntv, snpv;
    __shared__ float red[32];
    int tid = threadIdx.x, nt = blockDim.x;
    if (tid == 0) { sntv = 0; snpv = 0; }
    __syncthreads();
    for (int i = tid; i < NPTS; i += nt) {
        float2 p = g_pts[b * NPTS + i];
        px[i] = p.x; py[i] = p.y; pvv[i] = g_pv[b * NPTS + i];
        float2 t = g_pts[(BATCH + b) * NPTS + i];
        tx[i] = t.x; ty[i] = t.y; tvv[i] = g_pv[(BATCH + b) * NPTS + i];
    }
    __syncthreads();
    for (int i = tid; i < NPTS; i += nt) {
        if (tvv[i]) { int q = atomicAdd(&sntv, 1); cvx[q] = tx[i]; cvy[q] = ty[i]; }
        if (pvv[i]) { int q = atomicAdd(&snpv, 1); cpx[q] = px[i]; cpy[q] = py[i]; }
    }
    __syncthreads();
    int nT = sntv, nP = snpv;
    float amax = -1e9f;
    for (int p = tid; p < NPTS; p += nt) {
        if (!pvv[p]) continue;
        float x = px[p], y = py[p], val;
        if (nT == 0) val = 1e9f;
        else {
            float m = 3.4e38f;
            for (int t = 0; t < nT; t++) {
                float dx = x - cvx[t], dy = y - cvy[t];
                m = fminf(m, dx * dx + dy * dy);
            }
            val = sqrtf(m);
        }
        amax = fmaxf(amax, val);
    }
    for (int t = tid; t < NPTS; t += nt) {
        if (!tvv[t]) continue;
        float x = tx[t], y = ty[t], val;
        if (nP == 0) val = 1e9f;
        else {
            float m = 3.4e38f;
            for (int p = 0; p < nP; p++) {
                float dx = x - cpx[p], dy = y - cpy[p];
                m = fminf(m, dx * dx + dy * dy);
            }
            val = sqrtf(m);
        }
        amax = fmaxf(amax, val);
    }
    for (int off = 16; off; off >>= 1)
        amax = fmaxf(amax, __shfl_down_sync(0xffffffffu, amax, off));
    if ((tid & 31) == 0) red[tid >> 5] = amax;
    __syncthreads();
    if (tid < 32) {
        float v = (tid < (nt + 31) / 32) ? red[tid] : -1e9f;
        for (int off = 16; off; off >>= 1)
            v = fmaxf(v, __shfl_down_sync(0xffffffffu, v, off));
        if (tid == 0) {
            float diag = sqrtf((float)(HDIM * HDIM + WDIM * WDIM));
            float hd = v / diag;
            hd = fminf(fmaxf(hd, 0.0f), 0.1f);
            g_hd[b] = hd;
        }
    }
}

__global__ void k_mean(float* __restrict__ out) {
    if (threadIdx.x == 0) {
        float s = 0.0f;
        for (int i = 0; i < BATCH; i++) s += g_hd[i];
        out[0] = s / (float)BATCH;
    }
}

// ---------------- launch ----------------
extern "C" void kernel_launch(void* const* d_in, const int* in_sizes, int n_in,
                              void* d_out, int out_size) {
    const float* pred   = (const float*)d_in[0];
    const float* target = (const float*)d_in[1];
    float* out = (float*)d_out;

    k_zero<<<(NIMG * NBINS + 255) / 256, 256>>>();
    k_keys<<<1, 128>>>();
    k_sigmoid<<<(BATCH * NPIX + 255) / 256, 256>>>(pred);
    k_valid<<<(NIMG * (NPIX / 32) + 255) / 256, 256>>>(target);
    {
        dim3 g(NPIX / 256, NIMG);
        k_score<<<g, 256>>>();
    }
    k_cutoff<<<1, 128>>>();
    {
        dim3 g(NPIX / 256, NIMG);
        k_compact<<<g, 256>>>();
    }
    k_sort_emit<<<NIMG, 256>>>();
    k_hausdorff<<<BATCH, 1024>>>();
    k_mean<<<1, 32>>>(out);
}

// round 4
// speedup vs baseline: 3.9881x; 3.9881x over previous
#include <cuda_runtime.h>
#include <cuda_bf16.h>
#include <stdint.h>

// ---------------- problem constants ----------------
#define BATCH   64
#define HDIM    512
#define WDIM    512
#define NPIX    (HDIM*WDIM)          // 262144
#define NWORDS  (NPIX/32)            // 8192 valid-bit words per image
#define NIMG    (2*BATCH)            // 128 (pred images then target images)
#define NPTS    1000                 // SAMPLE_POINTS
#define CANDCAP 4096
#define PARTS   4

// ---------------- device scratch (static, allowed) ----------------
__device__ uint32_t g_keys[256];                    // split keys (pairs)
__device__ uint32_t g_validbits[NIMG*NWORDS];       // bit-packed valid mask
__device__ uint32_t g_nvalid[NIMG];
__device__ uint32_t g_tau[NIMG];                    // score-bits threshold
__device__ uint32_t g_candcnt[NIMG];
__device__ unsigned long long g_cand[(size_t)NIMG*CANDCAP];
__device__ float    g_lx[NIMG*NPTS];
__device__ float    g_ly[NIMG*NPTS];
__device__ int      g_np[NIMG];
__device__ unsigned int g_hdbits[BATCH];

// ---------------- threefry2x32 (exact JAX partitionable semantics) ----------------
__device__ __forceinline__ uint32_t rotl32(uint32_t x, int r) {
    return __funnelshift_l(x, x, r);
}
__device__ __forceinline__ void threefry2x32(uint32_t k0, uint32_t k1,
                                             uint32_t x0, uint32_t x1,
                                             uint32_t& o0, uint32_t& o1) {
    uint32_t ks2 = k0 ^ k1 ^ 0x1BD11BDAu;
    x0 += k0; x1 += k1;
#define TF_RND(r) { x0 += x1; x1 = rotl32(x1, r); x1 ^= x0; }
    TF_RND(13) TF_RND(15) TF_RND(26) TF_RND(6)   x0 += k1;  x1 += ks2 + 1u;
    TF_RND(17) TF_RND(29) TF_RND(16) TF_RND(24)  x0 += ks2; x1 += k0  + 2u;
    TF_RND(13) TF_RND(15) TF_RND(26) TF_RND(6)   x0 += k0;  x1 += k1  + 3u;
    TF_RND(17) TF_RND(29) TF_RND(16) TF_RND(24)  x0 += k1;  x1 += ks2 + 4u;
    TF_RND(13) TF_RND(15) TF_RND(26) TF_RND(6)   x0 += ks2; x1 += k0  + 5u;
#undef TF_RND
    o0 = x0; o1 = x1;
}
__device__ __forceinline__ float bits_to_uniform(uint32_t bits) {
    return __uint_as_float((bits >> 9) | 0x3F800000u) - 1.0f;
}

// ---------------- kernels ----------------
__global__ void k_zero() {
    int i = threadIdx.x;
    if (i < NIMG) { g_candcnt[i] = 0u; g_nvalid[i] = 0u; }
    if (i < BATCH) g_hdbits[i] = 0u;
}

// PARTITIONABLE split(key(1), 128): key_i = threefry(key, (0, i))
__global__ void k_keys() {
    int i = threadIdx.x;
    if (i < 128) {
        uint32_t o0, o1;
        threefry2x32(0u, 1u, 0u, (uint32_t)i, o0, o1);
        g_keys[2*i]     = o0;
        g_keys[2*i + 1] = o1;
    }
}

// Tiled Sobel: block = 8 output rows of one image. Sigmoid fused on load for
// pred images. Ballot -> valid word; popc -> per-image nvalid.
__global__ void __launch_bounds__(256) k_valid(const float* __restrict__ pred,
                                               const float* __restrict__ target) {
    __shared__ float s[10][514];
    __shared__ unsigned int blkcnt;
    int bx  = blockIdx.x;
    int b   = bx >> 6;           // image
    int r0  = (bx & 63) << 3;    // first output row
    int tid = threadIdx.x;
    if (tid == 0) blkcnt = 0u;
    bool isPred = (b < BATCH);
    const float* src = isPred ? (pred + (size_t)b * NPIX)
                              : (target + (size_t)(b - BATCH) * NPIX);
    // load 10 rows (halo included), 128 float4 per row
    for (int idx = tid; idx < 1280; idx += 256) {
        int lr = idx >> 7;
        int c4 = (idx & 127) << 2;
        int gr = r0 + lr - 1;
        float4 v;
        if (gr >= 0 && gr < HDIM) {
            v = *reinterpret_cast<const float4*>(src + ((size_t)gr << 9) + c4);
            if (isPred) {
                v.x = 1.0f / (1.0f + expf(-v.x));
                v.y = 1.0f / (1.0f + expf(-v.y));
                v.z = 1.0f / (1.0f + expf(-v.z));
                v.w = 1.0f / (1.0f + expf(-v.w));
            }
        } else v = make_float4(0.f, 0.f, 0.f, 0.f);
        s[lr][1 + c4] = v.x; s[lr][2 + c4] = v.y;
        s[lr][3 + c4] = v.z; s[lr][4 + c4] = v.w;
        if (c4 == 0) { s[lr][0] = 0.f; s[lr][513] = 0.f; }
    }
    __syncthreads();
    int w = tid >> 5, lane = tid & 31;
    unsigned int myc = 0;
    for (int u = w; u < 128; u += 8) {        // 8 rows x 16 segments
        int row8 = u >> 4, seg = u & 15;
        int sc = seg * 32 + lane + 1;
        float L0 = s[row8  ][sc-1], M0 = s[row8  ][sc], R0 = s[row8  ][sc+1];
        float L1 = s[row8+1][sc-1],                     R1 = s[row8+1][sc+1];
        float L2 = s[row8+2][sc-1], M2 = s[row8+2][sc], R2 = s[row8+2][sc+1];
        float gx = (R0 - L0) + 2.0f * (R1 - L1) + (R2 - L2);
        float gy = (L2 + 2.0f * M2 + R2) - (L0 + 2.0f * M0 + R0);
        float bm = sqrtf(gx * gx + gy * gy + 1e-8f);
        unsigned int word = __ballot_sync(0xffffffffu, bm > 0.1f);
        if (lane == 0) {
            g_validbits[b * NWORDS + (r0 + row8) * 16 + seg] = word;
            myc += __popc(word);
        }
    }
    if (lane == 0 && myc) atomicAdd(&blkcnt, myc);
    __syncthreads();
    if (tid == 0 && blkcnt) atomicAdd(&g_nvalid[b], blkcnt);
}

// Per-image score-bits threshold: expected ~2048 candidates.
__global__ void k_thresh() {
    int b = threadIdx.x;
    if (b < NIMG) {
        uint32_t nv = g_nvalid[b];
        uint32_t tb = 0u;                       // accept all valid
        if (nv > 2500u) {
            float ts = 2.0f + (1.0f - 2048.0f / (float)nv);
            tb = __float_as_uint(ts);
        }
        g_tau[b] = tb;
    }
}

// One pass: threefry noise, accept valid pixels with s_bits >= tau, push
// (s_bits<<32 | ~idx) with warp-aggregated atomics.
__global__ void __launch_bounds__(256) k_select() {
    int b = blockIdx.y;
    int i = blockIdx.x * 256 + threadIdx.x;      // pixel index
    int lane = threadIdx.x & 31;
    uint32_t k0 = g_keys[2*b], k1 = g_keys[2*b + 1];
    uint32_t tau = g_tau[b];
    uint32_t vw = g_validbits[b * NWORDS + (i >> 5)];
    bool v = (vw >> lane) & 1u;                  // (i&31) == lane
    uint32_t o0, o1;
    threefry2x32(k0, k1, 0u, (uint32_t)i, o0, o1);
    float u = bits_to_uniform(o0 ^ o1);
    float s = 2.0f + u;
    uint32_t sb = __float_as_uint(s);
    bool acc = v && (sb >= tau);
    unsigned int mask = __ballot_sync(0xffffffffu, acc);
    if (mask) {
        int leader = __ffs(mask) - 1;
        uint32_t base = 0;
        if (lane == leader) base = atomicAdd(&g_candcnt[b], (uint32_t)__popc(mask));
        base = __shfl_sync(0xffffffffu, base, leader);
        if (acc) {
            uint32_t pos = base + __popc(mask & ((1u << lane) - 1u));
            if (pos < CANDCAP)
                g_cand[(size_t)b * CANDCAP + pos] =
                    (((unsigned long long)sb) << 32) | (unsigned long long)(~(uint32_t)i);
        }
    }
}

// Sort candidates (score desc, index asc via key order), emit top min(1000,cnt)
// as compacted coordinate lists.
__global__ void __launch_bounds__(512) k_sort_emit() {
    __shared__ unsigned long long s[CANDCAP];
    int b = blockIdx.x, tid = threadIdx.x, nt = blockDim.x;
    unsigned int cnt = g_candcnt[b]; if (cnt > CANDCAP) cnt = CANDCAP;
    int need = (cnt < (unsigned)NPTS) ? (int)cnt : NPTS;
    int n = 2; while (n < (int)cnt) n <<= 1;
    for (int i = tid; i < n; i += nt)
        s[i] = (i < (int)cnt) ? g_cand[(size_t)b * CANDCAP + i] : 0ull;
    __syncthreads();
    for (int k = 2; k <= n; k <<= 1) {
        for (int j = k >> 1; j > 0; j >>= 1) {
            for (int i = tid; i < n; i += nt) {
                int ixj = i ^ j;
                if (ixj > i) {
                    unsigned long long a = s[i], bb = s[ixj];
                    if ((a > bb) == ((i & k) == 0)) { s[i] = bb; s[ixj] = a; }
                }
            }
            __syncthreads();
        }
    }
    for (int j = tid; j < need; j += nt) {
        unsigned long long key = s[n - 1 - j];
        uint32_t idx = ~(uint32_t)key;
        g_lx[b * NPTS + j] = (float)(idx >> 9);
        g_ly[b * NPTS + j] = (float)(idx & 511);
    }
    if (tid == 0) {
        if (cnt == 0u) {      // has_any == False: single center point
            g_np[b] = 1;
            g_lx[b * NPTS] = 256.0f;
            g_ly[b * NPTS] = 256.0f;
        } else g_np[b] = need;
    }
}

// Symmetric Hausdorff over compacted lists; PARTS blocks per image, atomicMax.
__global__ void __launch_bounds__(256) k_hausdorff() {
    __shared__ float stx[NPTS], sty[NPTS], spx[NPTS], spy[NPTS];
    __shared__ float red[8];
    int blk = blockIdx.x;
    int b = blk / PARTS, part = blk % PARTS;
    int np = g_np[b], ntt = g_np[BATCH + b];
    int tid = threadIdx.x;
    for (int i = tid; i < ntt; i += 256) {
        stx[i] = g_lx[(BATCH + b) * NPTS + i];
        sty[i] = g_ly[(BATCH + b) * NPTS + i];
    }
    for (int i = tid; i < np; i += 256) {
        spx[i] = g_lx[b * NPTS + i];
        spy[i] = g_ly[b * NPTS + i];
    }
    __syncthreads();
    float lmax = 0.0f;
    // dir A: pred chunk -> min over all target
    int ch = (np + PARTS - 1) / PARTS;
    int i0 = part * ch, i1 = (i0 + ch < np) ? (i0 + ch) : np;
    for (int ip = i0 + tid; ip < i1; ip += 256) {
        float x = spx[ip], y = spy[ip], m = 3.4e38f;
        for (int j = 0; j < ntt; j++) {
            float dx = x - stx[j], dy = y - sty[j];
            m = fminf(m, dx * dx + dy * dy);
        }
        lmax = fmaxf(lmax, sqrtf(m));
    }
    // dir B: target chunk -> min over all pred
    ch = (ntt + PARTS - 1) / PARTS;
    i0 = part * ch; i1 = (i0 + ch < ntt) ? (i0 + ch) : ntt;
    for (int it = i0 + tid; it < i1; it += 256) {
        float x = stx[it], y = sty[it], m = 3.4e38f;
        for (int j = 0; j < np; j++) {
            float dx = x - spx[j], dy = y - spy[j];
            m = fminf(m, dx * dx + dy * dy);
        }
        lmax = fmaxf(lmax, sqrtf(m));
    }
    for (int off = 16; off; off >>= 1)
        lmax = fmaxf(lmax, __shfl_down_sync(0xffffffffu, lmax, off));
    if ((tid & 31) == 0) red[tid >> 5] = lmax;
    __syncthreads();
    if (tid < 32) {
        float vv = (tid < 8) ? red[tid] : 0.0f;
        for (int off = 4; off; off >>= 1)
            vv = fmaxf(vv, __shfl_down_sync(0xffffffffu, vv, off));
        if (tid == 0) atomicMax(&g_hdbits[b], __float_as_uint(vv));
    }
}

__global__ void k_mean(float* __restrict__ out) {
    if (threadIdx.x == 0) {
        float diag = sqrtf((float)(HDIM * HDIM + WDIM * WDIM));
        float ssum = 0.0f;
        for (int i = 0; i < BATCH; i++) {
            float hd = __uint_as_float(g_hdbits[i]) / diag;
            hd = fminf(fmaxf(hd, 0.0f), 0.1f);
            ssum += hd;
        }
        out[0] = ssum / (float)BATCH;
    }
}

// ---------------- launch ----------------
extern "C" void kernel_launch(void* const* d_in, const int* in_sizes, int n_in,
                              void* d_out, int out_size) {
    const float* pred   = (const float*)d_in[0];
    const float* target = (const float*)d_in[1];
    float* out = (float*)d_out;

    k_zero<<<1, 256>>>();
    k_keys<<<1, 128>>>();
    k_valid<<<NIMG * 64, 256>>>(pred, target);
    k_thresh<<<1, 128>>>();
    {
        dim3 g(NPIX / 256, NIMG);
        k_select<<<g, 256>>>();
    }
    k_sort_emit<<<NIMG, 512>>>();
    k_hausdorff<<<BATCH * PARTS, 256>>>();
    k_mean<<<1, 32>>>(out);
}

// round 5
// speedup vs baseline: 5.4000x; 1.3540x over previous
#include <cuda_runtime.h>
#include <cuda_bf16.h>
#include <stdint.h>

// ---------------- problem constants ----------------
#define BATCH   64
#define HDIM    512
#define WDIM    512
#define NPIX    (HDIM*WDIM)          // 262144
#define NWORDS  (NPIX/32)            // 8192 valid-bit words per image
#define NIMG    (2*BATCH)            // 128 (pred then target images)
#define NPTS    1000
#define NPTS4   1004                 // padded stride (mult of 4 + sentinels)
#define CANDCAP 4096
#define PARTS   2
// fixed acceptance threshold on uniform noise: E[accepted] ~ 0.00723*nvalid
#define UTH     0.99277f

// ---------------- device scratch ----------------
__device__ uint32_t g_keys[256];
__device__ uint32_t g_validbits[NIMG*NWORDS];
__device__ uint32_t g_nvalid[NIMG];
__device__ uint32_t g_flag[NIMG];
__device__ uint32_t g_tau[NIMG];
__device__ uint32_t g_candcnt[NIMG];
__device__ unsigned long long g_cand[(size_t)NIMG*CANDCAP];
__device__ float    g_lx[NIMG*NPTS4];
__device__ float    g_ly[NIMG*NPTS4];
__device__ float    g_q [NIMG*NPTS4];
__device__ int      g_np[NIMG];
__device__ unsigned int g_hdbits[BATCH];

// ---------------- threefry2x32 (JAX partitionable semantics) ----------------
__device__ __forceinline__ uint32_t rotl32(uint32_t x, int r) {
    return __funnelshift_l(x, x, r);
}
__device__ __forceinline__ void threefry2x32(uint32_t k0, uint32_t k1,
                                             uint32_t x0, uint32_t x1,
                                             uint32_t& o0, uint32_t& o1) {
    uint32_t ks2 = k0 ^ k1 ^ 0x1BD11BDAu;
    x0 += k0; x1 += k1;
#define TF_RND(r) { x0 += x1; x1 = rotl32(x1, r); x1 ^= x0; }
    TF_RND(13) TF_RND(15) TF_RND(26) TF_RND(6)   x0 += k1;  x1 += ks2 + 1u;
    TF_RND(17) TF_RND(29) TF_RND(16) TF_RND(24)  x0 += ks2; x1 += k0  + 2u;
    TF_RND(13) TF_RND(15) TF_RND(26) TF_RND(6)   x0 += k0;  x1 += k1  + 3u;
    TF_RND(17) TF_RND(29) TF_RND(16) TF_RND(24)  x0 += k1;  x1 += ks2 + 4u;
    TF_RND(13) TF_RND(15) TF_RND(26) TF_RND(6)   x0 += ks2; x1 += k0  + 5u;
#undef TF_RND
    o0 = x0; o1 = x1;
}
__device__ __forceinline__ float bits_to_uniform(uint32_t bits) {
    return __uint_as_float((bits >> 9) | 0x3F800000u) - 1.0f;
}

// ---------------- kernels ----------------
__global__ void k_zero() {
    int i = threadIdx.x;
    if (i < NIMG) { g_candcnt[i] = 0u; g_nvalid[i] = 0u; g_flag[i] = 0u; }
    if (i < BATCH) g_hdbits[i] = 0u;
}

// partitionable split(key(1),128): key_i = threefry(key, (0,i))
__global__ void k_keys() {
    int i = threadIdx.x;
    if (i < 128) {
        uint32_t o0, o1;
        threefry2x32(0u, 1u, 0u, (uint32_t)i, o0, o1);
        g_keys[2*i] = o0; g_keys[2*i + 1] = o1;
    }
}

// Fused: tiled Sobel (sigmoid fused on load for pred) + threefry noise +
// fixed-threshold acceptance + warp-aggregated candidate push.
// Block = 8 output rows of one image, 256 threads.
__global__ void __launch_bounds__(256) k_fused(const float* __restrict__ pred,
                                               const float* __restrict__ target) {
    __shared__ float s[10][514];
    __shared__ unsigned int blkcnt;
    int bx  = blockIdx.x;
    int b   = bx >> 6;
    int r0  = (bx & 63) << 3;
    int tid = threadIdx.x;
    if (tid == 0) blkcnt = 0u;
    bool isPred = (b < BATCH);
    const float* src = isPred ? (pred + (size_t)b * NPIX)
                              : (target + (size_t)(b - BATCH) * NPIX);
    for (int idx = tid; idx < 1280; idx += 256) {
        int lr = idx >> 7;
        int c4 = (idx & 127) << 2;
        int gr = r0 + lr - 1;
        float4 v;
        if (gr >= 0 && gr < HDIM) {
            v = *reinterpret_cast<const float4*>(src + ((size_t)gr << 9) + c4);
            if (isPred) {
                v.x = 1.0f / (1.0f + expf(-v.x));
                v.y = 1.0f / (1.0f + expf(-v.y));
                v.z = 1.0f / (1.0f + expf(-v.z));
                v.w = 1.0f / (1.0f + expf(-v.w));
            }
        } else v = make_float4(0.f, 0.f, 0.f, 0.f);
        s[lr][1 + c4] = v.x; s[lr][2 + c4] = v.y;
        s[lr][3 + c4] = v.z; s[lr][4 + c4] = v.w;
        if (c4 == 0) { s[lr][0] = 0.f; s[lr][513] = 0.f; }
    }
    __syncthreads();
    uint32_t k0 = g_keys[2*b], k1 = g_keys[2*b + 1];
    int w = tid >> 5, lane = tid & 31;
    unsigned int myc = 0;
    for (int u = w; u < 128; u += 8) {            // 8 rows x 16 segments
        int row8 = u >> 4, seg = u & 15;
        int sc = seg * 32 + lane + 1;
        float L0 = s[row8  ][sc-1], M0 = s[row8  ][sc], R0 = s[row8  ][sc+1];
        float L1 = s[row8+1][sc-1],                     R1 = s[row8+1][sc+1];
        float L2 = s[row8+2][sc-1], M2 = s[row8+2][sc], R2 = s[row8+2][sc+1];
        float gx = (R0 - L0) + 2.0f * (R1 - L1) + (R2 - L2);
        float gy = (L2 + 2.0f * M2 + R2) - (L0 + 2.0f * M0 + R0);
        float bm = sqrtf(gx * gx + gy * gy + 1e-8f);
        bool v = bm > 0.1f;
        int gr = r0 + row8;
        unsigned int word = __ballot_sync(0xffffffffu, v);
        if (lane == 0) {
            g_validbits[b * NWORDS + gr * 16 + seg] = word;
            myc += __popc(word);
        }
        int i = (gr << 9) + seg * 32 + lane;       // pixel index
        uint32_t o0, o1;
        threefry2x32(k0, k1, 0u, (uint32_t)i, o0, o1);
        float uu = bits_to_uniform(o0 ^ o1);
        bool acc = v && (uu > UTH);
        unsigned int amask = __ballot_sync(0xffffffffu, acc);
        if (amask) {
            int leader = __ffs(amask) - 1;
            uint32_t base = 0;
            if (lane == leader) base = atomicAdd(&g_candcnt[b], (uint32_t)__popc(amask));
            base = __shfl_sync(0xffffffffu, base, leader);
            if (acc) {
                uint32_t pos = base + __popc(amask & ((1u << lane) - 1u));
                if (pos < CANDCAP) {
                    uint32_t sb = __float_as_uint(2.0f + uu);
                    g_cand[(size_t)b * CANDCAP + pos] =
                        (((unsigned long long)sb) << 32) | (unsigned long long)(~(uint32_t)i);
                }
            }
        }
    }
    if (lane == 0 && myc) atomicAdd(&blkcnt, myc);
    __syncthreads();
    if (tid == 0 && blkcnt) atomicAdd(&g_nvalid[b], blkcnt);
}

// Safety net: if candidates can't cover min(nvalid, NPTS), flag for rescue.
__global__ void k_check() {
    int b = threadIdx.x;
    if (b >= NIMG) return;
    uint32_t nv  = g_nvalid[b];
    uint32_t cnt = g_candcnt[b]; if (cnt > CANDCAP) cnt = CANDCAP;
    uint32_t needed = (nv < (uint32_t)NPTS) ? nv : (uint32_t)NPTS;
    if (cnt < needed) {
        g_flag[b] = 1u;
        g_candcnt[b] = 0u;
        uint32_t tb = 0u;                              // accept all valid
        if (nv > 2500u)
            tb = __float_as_uint(2.0f + (1.0f - 2048.0f / (float)nv));
        g_tau[b] = tb;
    }
}

// Rescue path (adaptive tau, reads stored validbits). No-op when unflagged.
__global__ void __launch_bounds__(256) k_rescue() {
    int b = blockIdx.x;
    if (!g_flag[b]) return;
    int tid = threadIdx.x, lane = tid & 31;
    uint32_t k0 = g_keys[2*b], k1 = g_keys[2*b + 1];
    uint32_t tau = g_tau[b];
    for (int chunk = 0; chunk < NPIX / 256; chunk++) {
        int i = chunk * 256 + tid;
        uint32_t vw = g_validbits[b * NWORDS + (i >> 5)];
        bool v = (vw >> lane) & 1u;
        uint32_t o0, o1;
        threefry2x32(k0, k1, 0u, (uint32_t)i, o0, o1);
        float uu = bits_to_uniform(o0 ^ o1);
        uint32_t sb = __float_as_uint(2.0f + uu);
        bool acc = v && (sb >= tau);
        unsigned int amask = __ballot_sync(0xffffffffu, acc);
        if (amask) {
            int leader = __ffs(amask) - 1;
            uint32_t base = 0;
            if (lane == leader) base = atomicAdd(&g_candcnt[b], (uint32_t)__popc(amask));
            base = __shfl_sync(0xffffffffu, base, leader);
            if (acc) {
                uint32_t pos = base + __popc(amask & ((1u << lane) - 1u));
                if (pos < CANDCAP)
                    g_cand[(size_t)b * CANDCAP + pos] =
                        (((unsigned long long)sb) << 32) | (unsigned long long)(~(uint32_t)i);
            }
        }
    }
}

// Sort candidates (score desc, idx asc), emit compacted coords + q = x^2+y^2,
// pad to multiple of 4 with far-away sentinels.
__global__ void __launch_bounds__(512) k_sort_emit() {
    __shared__ unsigned long long s[CANDCAP];
    int b = blockIdx.x, tid = threadIdx.x, nt = blockDim.x;
    unsigned int cnt = g_candcnt[b]; if (cnt > CANDCAP) cnt = CANDCAP;
    int need = (cnt < (unsigned)NPTS) ? (int)cnt : NPTS;
    int n = 2; while (n < (int)cnt) n <<= 1;
    for (int i = tid; i < n; i += nt)
        s[i] = (i < (int)cnt) ? g_cand[(size_t)b * CANDCAP + i] : 0ull;
    __syncthreads();
    for (int k = 2; k <= n; k <<= 1) {
        for (int j = k >> 1; j > 0; j >>= 1) {
            for (int i = tid; i < n; i += nt) {
                int ixj = i ^ j;
                if (ixj > i) {
                    unsigned long long a = s[i], bb = s[ixj];
                    if ((a > bb) == ((i & k) == 0)) { s[i] = bb; s[ixj] = a; }
                }
            }
            __syncthreads();
        }
    }
    int npts = (cnt == 0u) ? 1 : need;
    int pad  = (npts + 3) & ~3;
    for (int j = tid; j < pad; j += nt) {
        float x, y, q;
        if (j < npts) {
            if (cnt == 0u) { x = 256.0f; y = 256.0f; }
            else {
                unsigned long long key = s[n - 1 - j];
                uint32_t idx = ~(uint32_t)key;
                x = (float)(idx >> 9); y = (float)(idx & 511);
            }
            q = x * x + y * y;
        } else { x = 0.0f; y = 0.0f; q = 3.0e38f; }   // sentinel: never the min
        g_lx[b * NPTS4 + j] = x;
        g_ly[b * NPTS4 + j] = y;
        g_q [b * NPTS4 + j] = q;
    }
    if (tid == 0) g_np[b] = npts;
}

// Symmetric Hausdorff: d2 = x^2+y^2 + min_j(q_j - 2x*tx_j - 2y*ty_j), all exact
// integers < 2^21 in fp32. 2 register queries/thread, float4 smem j-loop.
__global__ void __launch_bounds__(256) k_hausdorff() {
    __shared__ __align__(16) float spx[NPTS4], spy[NPTS4], sqp[NPTS4];
    __shared__ __align__(16) float stx[NPTS4], sty[NPTS4], sqt[NPTS4];
    __shared__ float red[8];
    int blk = blockIdx.x;
    int b = blk >> 1, part = blk & 1;
    int np = g_np[b], ntt = g_np[BATCH + b];
    int np4 = (np + 3) & ~3, nt4 = (ntt + 3) & ~3;
    int tid = threadIdx.x;
    for (int i = tid; i < np4; i += 256) {
        spx[i] = g_lx[b * NPTS4 + i];
        spy[i] = g_ly[b * NPTS4 + i];
        sqp[i] = g_q [b * NPTS4 + i];
    }
    for (int i = tid; i < nt4; i += 256) {
        stx[i] = g_lx[(BATCH + b) * NPTS4 + i];
        sty[i] = g_ly[(BATCH + b) * NPTS4 + i];
        sqt[i] = g_q [(BATCH + b) * NPTS4 + i];
    }
    __syncthreads();
    float lmax = 0.0f;
    // dir A: pred chunk -> min over target
    {
        int ch = (np + PARTS - 1) / PARTS;
        int i0 = part * ch, i1 = (i0 + ch < np) ? (i0 + ch) : np;
        for (int base = i0; base < i1; base += 512) {
            int ia = base + tid, ib = base + tid + 256;
            bool va = ia < i1, vb = ib < i1;
            float xa = va ? spx[ia] : 0.f, ya = va ? spy[ia] : 0.f;
            float xb = vb ? spx[ib] : 0.f, yb = vb ? spy[ib] : 0.f;
            float nxa = -2.f * xa, nya = -2.f * ya;
            float nxb = -2.f * xb, nyb = -2.f * yb;
            float ma = 3.4e38f, mb = 3.4e38f;
            for (int j = 0; j < nt4; j += 4) {
                float4 t4 = *reinterpret_cast<float4*>(&stx[j]);
                float4 y4 = *reinterpret_cast<float4*>(&sty[j]);
                float4 q4 = *reinterpret_cast<float4*>(&sqt[j]);
                ma = fminf(ma, fmaf(t4.x, nxa, fmaf(y4.x, nya, q4.x)));
                ma = fminf(ma, fmaf(t4.y, nxa, fmaf(y4.y, nya, q4.y)));
                ma = fminf(ma, fmaf(t4.z, nxa, fmaf(y4.z, nya, q4.z)));
                ma = fminf(ma, fmaf(t4.w, nxa, fmaf(y4.w, nya, q4.w)));
                mb = fminf(mb, fmaf(t4.x, nxb, fmaf(y4.x, nyb, q4.x)));
                mb = fminf(mb, fmaf(t4.y, nxb, fmaf(y4.y, nyb, q4.y)));
                mb = fminf(mb, fmaf(t4.z, nxb, fmaf(y4.z, nyb, q4.z)));
                mb = fminf(mb, fmaf(t4.w, nxb, fmaf(y4.w, nyb, q4.w)));
            }
            if (va) lmax = fmaxf(lmax, sqrtf(fmaxf(ma + (xa*xa + ya*ya), 0.f)));
            if (vb) lmax = fmaxf(lmax, sqrtf(fmaxf(mb + (xb*xb + yb*yb), 0.f)));
        }
    }
    // dir B: target chunk -> min over pred
    {
        int ch = (ntt + PARTS - 1) / PARTS;
        int i0 = part * ch, i1 = (i0 + ch < ntt) ? (i0 + ch) : ntt;
        for (int base = i0; base < i1; base += 512) {
            int ia = base + tid, ib = base + tid + 256;
            bool va = ia < i1, vb = ib < i1;
            float xa = va ? stx[ia] : 0.f, ya = va ? sty[ia] : 0.f;
            float xb = vb ? stx[ib] : 0.f, yb = vb ? sty[ib] : 0.f;
            float nxa = -2.f * xa, nya = -2.f * ya;
            float nxb = -2.f * xb, nyb = -2.f * yb;
            float ma = 3.4e38f, mb = 3.4e38f;
            for (int j = 0; j < np4; j += 4) {
                float4 t4 = *reinterpret_cast<float4*>(&spx[j]);
                float4 y4 = *reinterpret_cast<float4*>(&spy[j]);
                float4 q4 = *reinterpret_cast<float4*>(&sqp[j]);
                ma = fminf(ma, fmaf(t4.x, nxa, fmaf(y4.x, nya, q4.x)));
                ma = fminf(ma, fmaf(t4.y, nxa, fmaf(y4.y, nya, q4.y)));
                ma = fminf(ma, fmaf(t4.z, nxa, fmaf(y4.z, nya, q4.z)));
                ma = fminf(ma, fmaf(t4.w, nxa, fmaf(y4.w, nya, q4.w)));
                mb = fminf(mb, fmaf(t4.x, nxb, fmaf(y4.x, nyb, q4.x)));
                mb = fminf(mb, fmaf(t4.y, nxb, fmaf(y4.y, nyb, q4.y)));
                mb = fminf(mb, fmaf(t4.z, nxb, fmaf(y4.z, nyb, q4.z)));
                mb = fminf(mb, fmaf(t4.w, nxb, fmaf(y4.w, nyb, q4.w)));
            }
            if (va) lmax = fmaxf(lmax, sqrtf(fmaxf(ma + (xa*xa + ya*ya), 0.f)));
            if (vb) lmax = fmaxf(lmax, sqrtf(fmaxf(mb + (xb*xb + yb*yb), 0.f)));
        }
    }
    for (int off = 16; off; off >>= 1)
        lmax = fmaxf(lmax, __shfl_down_sync(0xffffffffu, lmax, off));
    if ((tid & 31) == 0) red[tid >> 5] = lmax;
    __syncthreads();
    if (tid < 32) {
        float vv = (tid < 8) ? red[tid] : 0.0f;
        for (int off = 4; off; off >>= 1)
            vv = fmaxf(vv, __shfl_down_sync(0xffffffffu, vv, off));
        if (tid == 0) atomicMax(&g_hdbits[b], __float_as_uint(vv));
    }
}

__global__ void k_mean(float* __restrict__ out) {
    if (threadIdx.x == 0) {
        float diag = sqrtf((float)(HDIM * HDIM + WDIM * WDIM));
        float ssum = 0.0f;
        for (int i = 0; i < BATCH; i++) {
            float hd = __uint_as_float(g_hdbits[i]) / diag;
            hd = fminf(fmaxf(hd, 0.0f), 0.1f);
            ssum += hd;
        }
        out[0] = ssum / (float)BATCH;
    }
}

// ---------------- launch ----------------
extern "C" void kernel_launch(void* const* d_in, const int* in_sizes, int n_in,
                              void* d_out, int out_size) {
    const float* pred   = (const float*)d_in[0];
    const float* target = (const float*)d_in[1];
    float* out = (float*)d_out;

    k_zero<<<1, 256>>>();
    k_keys<<<1, 128>>>();
    k_fused<<<NIMG * 64, 256>>>(pred, target);
    k_check<<<1, 128>>>();
    k_rescue<<<NIMG, 256>>>();
    k_sort_emit<<<NIMG, 512>>>();
    k_hausdorff<<<BATCH * PARTS, 256>>>();
    k_mean<<<1, 32>>>(out);
}